// round 16
// baseline (speedup 1.0000x reference)
#include <cuda_runtime.h>
#include <cuda_bf16.h>
#include <math.h>
#include <stdint.h>

// Problem constants: N=50000 nodes, E=300000 edges, F_IN=128, H=256, C=32.
#define MAXN 50000
#define MAXE 300000
#define HDIM 256

// Scratch (no allocations allowed). Referenced ONLY from device code.
__device__ float g_dinv[MAXN];
__device__ int   g_cnt[MAXN];
__device__ int   g_pos[MAXN];
__device__ int   g_rowptr[MAXN + 1];
__device__ int   g_srcs[MAXE];
__device__ float g_H[MAXN * HDIM];    // GEMM output (messages source)
__device__ float g_A[MAXN * HDIM];    // layer-1 aggregate
__device__ float g_A2[MAXN * HDIM];   // layer-2 aggregate
__device__ float g_WT[HDIM * HDIM];   // transposed weights [n][k]

// ---------------------------------------------------------------------------
// Helpers
// ---------------------------------------------------------------------------
__device__ __forceinline__ uint32_t smem_u32(const void* p) {
    uint32_t a;
    asm("{ .reg .u64 t; cvta.to.shared.u64 t, %1; cvt.u32.u64 %0, t; }"
        : "=r"(a) : "l"(p));
    return a;
}
__device__ __forceinline__ uint32_t to_tf32(float x) {
    float r;
    asm("cvt.rna.tf32.f32 %0, %1;" : "=f"(r) : "f"(x));
    return __float_as_uint(r);
}
__device__ __forceinline__ void ldsm_x4(uint32_t& r0, uint32_t& r1,
                                        uint32_t& r2, uint32_t& r3,
                                        uint32_t addr) {
    asm volatile("ldmatrix.sync.aligned.m8n8.x4.shared.b16 {%0,%1,%2,%3}, [%4];"
                 : "=r"(r0), "=r"(r1), "=r"(r2), "=r"(r3) : "r"(addr));
}
__device__ __forceinline__ void mma_tf32(float* d, const uint32_t* a,
                                         const uint32_t* b) {
    asm volatile(
        "mma.sync.aligned.m16n8k8.row.col.f32.tf32.tf32.f32 "
        "{%0,%1,%2,%3}, {%4,%5,%6,%7}, {%8,%9}, {%0,%1,%2,%3};"
        : "+f"(d[0]), "+f"(d[1]), "+f"(d[2]), "+f"(d[3])
        : "r"(a[0]), "r"(a[1]), "r"(a[2]), "r"(a[3]), "r"(b[0]), "r"(b[1]));
}

// ---------------------------------------------------------------------------
// CSR build (dst-major) + dinv
// ---------------------------------------------------------------------------
__global__ void zero_cnt_kernel(int n) {
    int i = blockIdx.x * blockDim.x + threadIdx.x;
    if (i < n) { g_cnt[i] = 0; g_pos[i] = 0; }
}
__global__ void count_kernel(const int* __restrict__ dst, int e) {
    int i = blockIdx.x * blockDim.x + threadIdx.x;
    if (i < e) atomicAdd(&g_cnt[dst[i]], 1);
}
__global__ void scan_kernel(int n, int e) {
    __shared__ int part[1024];
    const int t = threadIdx.x;
    const int per = (n + 1023) / 1024;
    const int start = t * per;
    int sum = 0;
    for (int i = 0; i < per; i++) {
        int idx = start + i;
        if (idx < n) { g_rowptr[idx] = sum; sum += g_cnt[idx]; }
    }
    part[t] = sum;
    __syncthreads();
    for (int off = 1; off < 1024; off <<= 1) {
        int v = (t >= off) ? part[t - off] : 0;
        __syncthreads();
        part[t] += v;
        __syncthreads();
    }
    int offset = (t > 0) ? part[t - 1] : 0;
    for (int i = 0; i < per; i++) {
        int idx = start + i;
        if (idx < n) g_rowptr[idx] += offset;
    }
    if (t == 0) g_rowptr[n] = e;
    for (int i = t; i < n; i += 1024)
        g_dinv[i] = rsqrtf((float)g_cnt[i] + 1.0f);   // +1 self-loop
}
__global__ void fill_kernel(const int* __restrict__ src,
                            const int* __restrict__ dst, int e) {
    int i = blockIdx.x * blockDim.x + threadIdx.x;
    if (i < e) {
        int d = dst[i];
        int p = atomicAdd(&g_pos[d], 1);
        g_srcs[g_rowptr[d] + p] = src[i];
    }
}

// ---------------------------------------------------------------------------
// Weight transpose: g_WT[n][k] = W[k][n].  W is [K][NC].
// ---------------------------------------------------------------------------
__global__ void wtrans_kernel(const float* __restrict__ W, int K, int NC) {
    __shared__ float t[32][33];
    int k0 = blockIdx.x * 32, n0 = blockIdx.y * 32;
    int tx = threadIdx.x, ty = threadIdx.y;           // 32 x 8
#pragma unroll
    for (int j = 0; j < 32; j += 8) {
        int k = k0 + ty + j, n = n0 + tx;
        t[ty + j][tx] = (k < K && n < NC) ? W[(size_t)k * NC + n] : 0.0f;
    }
    __syncthreads();
#pragma unroll
    for (int j = 0; j < 32; j += 8) {
        int n = n0 + ty + j, k = k0 + tx;
        if (k < K && n < NC) g_WT[(size_t)n * K + k] = t[tx][ty + j];
    }
}

// ---------------------------------------------------------------------------
// TF32 mma.sync GEMM:  g_H[M,256] = op(A)[M,K] @ W[K,256]  (B from g_WT)
// CTA = 128x128, BK=16, 256 threads (8 warps as 2x4, 64x32/warp).
// ---------------------------------------------------------------------------
template <int K, bool RELU, int SEL>
__global__ void __launch_bounds__(256)
gemm_mma(const float* __restrict__ Ain, int M) {
    const float* A = (SEL == 0) ? Ain : g_A;
    float* Cout = g_H;

    __shared__ float As[2][128 * 16];
    __shared__ float Bs[2][128 * 16];

    const int tid = threadIdx.x;
    const int wid = tid >> 5, lane = tid & 31;
    const int warp_m = wid >> 2, warp_n = wid & 3;
    const int row0 = blockIdx.x * 128;
    const int col0 = blockIdx.y * 128;

    const uint32_t baseA = smem_u32(As);
    const uint32_t baseB = smem_u32(Bs);

    uint4 ra[2], rb[2];
    auto ld_g = [&](int t) {
#pragma unroll
        for (int j = 0; j < 2; j++) {
            int idx = j * 256 + tid;
            int r = idx >> 2, c = idx & 3;
            int gr = row0 + r;
            float4 v = make_float4(0.f, 0.f, 0.f, 0.f);
            if (gr < M) v = *(const float4*)&A[(size_t)gr * K + t * 16 + c * 4];
            if (RELU) {
                v.x = fmaxf(v.x, 0.f); v.y = fmaxf(v.y, 0.f);
                v.z = fmaxf(v.z, 0.f); v.w = fmaxf(v.w, 0.f);
            }
            ra[j].x = to_tf32(v.x); ra[j].y = to_tf32(v.y);
            ra[j].z = to_tf32(v.z); ra[j].w = to_tf32(v.w);
            float4 w = *(const float4*)&g_WT[(size_t)(col0 + r) * K + t * 16 + c * 4];
            rb[j].x = to_tf32(w.x); rb[j].y = to_tf32(w.y);
            rb[j].z = to_tf32(w.z); rb[j].w = to_tf32(w.w);
        }
    };
    auto st_s = [&](int b) {
#pragma unroll
        for (int j = 0; j < 2; j++) {
            int idx = j * 256 + tid;
            int r = idx >> 2, c = idx & 3;
            uint32_t off = (uint32_t)(r * 64 + ((c ^ ((r >> 1) & 3)) << 4));
            *(uint4*)((char*)As[b] + off) = ra[j];
            *(uint4*)((char*)Bs[b] + off) = rb[j];
        }
    };

    uint32_t a_row[4], a_sw[4];
#pragma unroll
    for (int mi = 0; mi < 4; mi++) {
        int row = warp_m * 64 + mi * 16 + ((lane >> 3) & 1) * 8 + (lane & 7);
        a_row[mi] = (uint32_t)(row * 64);
        a_sw[mi] = (uint32_t)((row >> 1) & 3);
    }
    const uint32_t a_chi = (uint32_t)((lane >> 4) & 1);
    uint32_t b_row[2], b_sw[2];
#pragma unroll
    for (int njp = 0; njp < 2; njp++) {
        int n = warp_n * 32 + njp * 16 + ((lane >> 4) & 1) * 8 + (lane & 7);
        b_row[njp] = (uint32_t)(n * 64);
        b_sw[njp] = (uint32_t)((n >> 1) & 3);
    }
    const uint32_t b_chi = (uint32_t)((lane >> 3) & 1);

    float acc[4][4][4];
#pragma unroll
    for (int mi = 0; mi < 4; mi++)
#pragma unroll
        for (int nj = 0; nj < 4; nj++)
#pragma unroll
            for (int i = 0; i < 4; i++) acc[mi][nj][i] = 0.0f;

    constexpr int NT = K / 16;

    ld_g(0);
    st_s(0);
    __syncthreads();

    for (int t = 0; t < NT; t++) {
        int cur = t & 1;
        bool more = (t + 1) < NT;
        if (more) ld_g(t + 1);

        uint32_t bA = baseA + (uint32_t)cur * 8192;
        uint32_t bB = baseB + (uint32_t)cur * 8192;
#pragma unroll
        for (int s = 0; s < 2; s++) {
            uint32_t af[4][4];
#pragma unroll
            for (int mi = 0; mi < 4; mi++) {
                uint32_t ch = 2 * s + a_chi;
                uint32_t addr = bA + a_row[mi] + ((ch ^ a_sw[mi]) << 4);
                ldsm_x4(af[mi][0], af[mi][1], af[mi][2], af[mi][3], addr);
            }
            uint32_t bf[4][2];
#pragma unroll
            for (int njp = 0; njp < 2; njp++) {
                uint32_t ch = 2 * s + b_chi;
                uint32_t addr = bB + b_row[njp] + ((ch ^ b_sw[njp]) << 4);
                uint32_t r0, r1, r2, r3;
                ldsm_x4(r0, r1, r2, r3, addr);
                bf[2 * njp][0] = r0;     bf[2 * njp][1] = r1;
                bf[2 * njp + 1][0] = r2; bf[2 * njp + 1][1] = r3;
            }
#pragma unroll
            for (int mi = 0; mi < 4; mi++)
#pragma unroll
                for (int nj = 0; nj < 4; nj++)
                    mma_tf32(acc[mi][nj], af[mi], bf[nj]);
        }

        if (more) st_s(cur ^ 1);
        __syncthreads();
    }

    const int g = lane >> 2, tg = lane & 3;
#pragma unroll
    for (int mi = 0; mi < 4; mi++) {
        int R0 = row0 + warp_m * 64 + mi * 16 + g;
        int R1 = R0 + 8;
#pragma unroll
        for (int nj = 0; nj < 4; nj++) {
            int cc = col0 + warp_n * 32 + nj * 8 + tg * 2;
            if (R0 < M)
                *(float2*)&Cout[(size_t)R0 * HDIM + cc] =
                    make_float2(acc[mi][nj][0], acc[mi][nj][1]);
            if (R1 < M)
                *(float2*)&Cout[(size_t)R1 * HDIM + cc] =
                    make_float2(acc[mi][nj][2], acc[mi][nj][3]);
        }
    }
}

// ---------------------------------------------------------------------------
// Classifier TF32 mma GEMM: out[M,32] = relu(g_A2)[M,256] @ Wc + bc.
// ---------------------------------------------------------------------------
__global__ void __launch_bounds__(256)
gemm_cls(const float* __restrict__ bias, float* __restrict__ out, int M) {
    constexpr int K = 256;
    __shared__ float As[2][128 * 16];
    __shared__ float Bs[2][32 * 16];

    const int tid = threadIdx.x;
    const int wid = tid >> 5, lane = tid & 31;
    const int row0 = blockIdx.x * 128;

    const uint32_t baseA = smem_u32(As);
    const uint32_t baseB = smem_u32(Bs);

    uint4 ra[2], rb;
    auto ld_g = [&](int t) {
#pragma unroll
        for (int j = 0; j < 2; j++) {
            int idx = j * 256 + tid;
            int r = idx >> 2, c = idx & 3;
            int gr = row0 + r;
            float4 v = make_float4(0.f, 0.f, 0.f, 0.f);
            if (gr < M) v = *(const float4*)&g_A2[(size_t)gr * K + t * 16 + c * 4];
            v.x = fmaxf(v.x, 0.f); v.y = fmaxf(v.y, 0.f);
            v.z = fmaxf(v.z, 0.f); v.w = fmaxf(v.w, 0.f);
            ra[j].x = to_tf32(v.x); ra[j].y = to_tf32(v.y);
            ra[j].z = to_tf32(v.z); ra[j].w = to_tf32(v.w);
        }
        if (tid < 128) {
            int r = tid >> 2, c = tid & 3;
            float4 w = *(const float4*)&g_WT[(size_t)r * K + t * 16 + c * 4];
            rb.x = to_tf32(w.x); rb.y = to_tf32(w.y);
            rb.z = to_tf32(w.z); rb.w = to_tf32(w.w);
        }
    };
    auto st_s = [&](int b) {
#pragma unroll
        for (int j = 0; j < 2; j++) {
            int idx = j * 256 + tid;
            int r = idx >> 2, c = idx & 3;
            uint32_t off = (uint32_t)(r * 64 + ((c ^ ((r >> 1) & 3)) << 4));
            *(uint4*)((char*)As[b] + off) = ra[j];
        }
        if (tid < 128) {
            int r = tid >> 2, c = tid & 3;
            uint32_t off = (uint32_t)(r * 64 + ((c ^ ((r >> 1) & 3)) << 4));
            *(uint4*)((char*)Bs[b] + off) = rb;
        }
    };

    int a_r = wid * 16 + ((lane >> 3) & 1) * 8 + (lane & 7);
    const uint32_t a_row = (uint32_t)(a_r * 64);
    const uint32_t a_sw = (uint32_t)((a_r >> 1) & 3);
    const uint32_t a_chi = (uint32_t)((lane >> 4) & 1);
    uint32_t b_row[2], b_sw[2];
#pragma unroll
    for (int njp = 0; njp < 2; njp++) {
        int n = njp * 16 + ((lane >> 4) & 1) * 8 + (lane & 7);
        b_row[njp] = (uint32_t)(n * 64);
        b_sw[njp] = (uint32_t)((n >> 1) & 3);
    }
    const uint32_t b_chi = (uint32_t)((lane >> 3) & 1);

    float acc[4][4];
#pragma unroll
    for (int nj = 0; nj < 4; nj++)
#pragma unroll
        for (int i = 0; i < 4; i++) acc[nj][i] = 0.0f;

    constexpr int NT = K / 16;

    ld_g(0);
    st_s(0);
    __syncthreads();

    for (int t = 0; t < NT; t++) {
        int cur = t & 1;
        bool more = (t + 1) < NT;
        if (more) ld_g(t + 1);

        uint32_t bA = baseA + (uint32_t)cur * 8192;
        uint32_t bB = baseB + (uint32_t)cur * 2048;
#pragma unroll
        for (int s = 0; s < 2; s++) {
            uint32_t af[4];
            {
                uint32_t ch = 2 * s + a_chi;
                uint32_t addr = bA + a_row + ((ch ^ a_sw) << 4);
                ldsm_x4(af[0], af[1], af[2], af[3], addr);
            }
            uint32_t bf[4][2];
#pragma unroll
            for (int njp = 0; njp < 2; njp++) {
                uint32_t ch = 2 * s + b_chi;
                uint32_t addr = bB + b_row[njp] + ((ch ^ b_sw[njp]) << 4);
                uint32_t r0, r1, r2, r3;
                ldsm_x4(r0, r1, r2, r3, addr);
                bf[2 * njp][0] = r0;     bf[2 * njp][1] = r1;
                bf[2 * njp + 1][0] = r2; bf[2 * njp + 1][1] = r3;
            }
#pragma unroll
            for (int nj = 0; nj < 4; nj++)
                mma_tf32(acc[nj], af, bf[nj]);
        }

        if (more) st_s(cur ^ 1);
        __syncthreads();
    }

    const int g = lane >> 2, tg = lane & 3;
    int R0 = row0 + wid * 16 + g;
    int R1 = R0 + 8;
#pragma unroll
    for (int nj = 0; nj < 4; nj++) {
        int cc = nj * 8 + tg * 2;
        float2 bb = *(const float2*)&bias[cc];
        if (R0 < M)
            *(float2*)&out[(size_t)R0 * 32 + cc] =
                make_float2(acc[nj][0] + bb.x, acc[nj][1] + bb.y);
        if (R1 < M)
            *(float2*)&out[(size_t)R1 * 32 + cc] =
                make_float2(acc[nj][2] + bb.x, acc[nj][3] + bb.y);
    }
}

// ---------------------------------------------------------------------------
// Gather aggregation: out[i,:] = bias + dinv_i^2*H[i,:] + sum_j norm*H[src_j,:]
// Warp per node, 32 lanes x 8 floats. Warp-cooperative index prefetch +
// 4-edge batched row loads (MLP 8 on the heavy L2 loads).
// ---------------------------------------------------------------------------
__global__ void __launch_bounds__(256)
gather_kernel(const float* __restrict__ bias, int n, int which) {
    int node = blockIdx.x * 8 + (threadIdx.x >> 5);
    if (node >= n) return;
    int lane = threadIdx.x & 31;
    int c0 = lane * 8;

    float* out = which ? g_A2 : g_A;
    float di = g_dinv[node];
    float s2 = di * di;

    float4 b0 = *(const float4*)&bias[c0];
    float4 b1 = *(const float4*)&bias[c0 + 4];
    float4 h0 = *(const float4*)&g_H[(size_t)node * HDIM + c0];
    float4 h1 = *(const float4*)&g_H[(size_t)node * HDIM + c0 + 4];
    float4 a0 = make_float4(b0.x + s2 * h0.x, b0.y + s2 * h0.y,
                            b0.z + s2 * h0.z, b0.w + s2 * h0.w);
    float4 a1 = make_float4(b1.x + s2 * h1.x, b1.y + s2 * h1.y,
                            b1.z + s2 * h1.z, b1.w + s2 * h1.w);

    int beg = g_rowptr[node], end = g_rowptr[node + 1];

    for (int j0 = beg; j0 < end; j0 += 32) {
        int m = end - j0;
        if (m > 32) m = 32;
        // Warp-parallel prefetch of indices + dinv (1 L2 trip for all edges)
        int sj = 0;
        float dvj = 0.0f;
        if (lane < m) {
            sj = g_srcs[j0 + lane];
            dvj = g_dinv[sj];
        }
        int j = 0;
        for (; j + 4 <= m; j += 4) {
            float4 u0[4], u1[4];
            float nm[4];
#pragma unroll
            for (int q = 0; q < 4; q++) {
                int s = __shfl_sync(0xffffffffu, sj, j + q);
                float dv = __shfl_sync(0xffffffffu, dvj, j + q);
                nm[q] = di * dv;
                const float* p = &g_H[(size_t)s * HDIM + c0];
                u0[q] = *(const float4*)p;
                u1[q] = *(const float4*)(p + 4);
            }
#pragma unroll
            for (int q = 0; q < 4; q++) {
                a0.x += nm[q] * u0[q].x; a0.y += nm[q] * u0[q].y;
                a0.z += nm[q] * u0[q].z; a0.w += nm[q] * u0[q].w;
                a1.x += nm[q] * u1[q].x; a1.y += nm[q] * u1[q].y;
                a1.z += nm[q] * u1[q].z; a1.w += nm[q] * u1[q].w;
            }
        }
        for (; j < m; j++) {
            int s = __shfl_sync(0xffffffffu, sj, j);
            float dv = __shfl_sync(0xffffffffu, dvj, j);
            float nm = di * dv;
            const float* p = &g_H[(size_t)s * HDIM + c0];
            float4 u0 = *(const float4*)p;
            float4 u1 = *(const float4*)(p + 4);
            a0.x += nm * u0.x; a0.y += nm * u0.y;
            a0.z += nm * u0.z; a0.w += nm * u0.w;
            a1.x += nm * u1.x; a1.y += nm * u1.y;
            a1.z += nm * u1.z; a1.w += nm * u1.w;
        }
    }
    *(float4*)&out[(size_t)node * HDIM + c0]     = a0;
    *(float4*)&out[(size_t)node * HDIM + c0 + 4] = a1;
}

// ---------------------------------------------------------------------------
// Launch
// ---------------------------------------------------------------------------
extern "C" void kernel_launch(void* const* d_in, const int* in_sizes, int n_in,
                              void* d_out, int out_size) {
    const float* x  = (const float*)d_in[0];
    const int* eidx = (const int*)d_in[1];
    const float* W1 = (const float*)d_in[2];
    const float* b1 = (const float*)d_in[3];
    const float* W2 = (const float*)d_in[4];
    const float* b2 = (const float*)d_in[5];
    const float* Wc = (const float*)d_in[6];
    const float* bc = (const float*)d_in[7];
    float* out = (float*)d_out;

    const int F_IN = 128;
    const int N = in_sizes[0] / F_IN;   // 50000
    const int E = in_sizes[1] / 2;      // 300000
    const int* src = eidx;
    const int* dst = eidx + E;

    // ---- CSR build (dst-major) + dinv ----
    zero_cnt_kernel<<<(N + 255) / 256, 256>>>(N);
    count_kernel<<<(E + 255) / 256, 256>>>(dst, E);
    scan_kernel<<<1, 1024>>>(N, E);
    fill_kernel<<<(E + 255) / 256, 256>>>(src, dst, E);

    const int RB = (N + 127) / 128;     // 391 row blocks
    dim3 ggrid(RB, HDIM / 128);         // 391 x 2
    const int GB = (N + 7) / 8;         // gather blocks

    // layer 1: g_H = X @ W1 ; g_A = gather(b1)
    wtrans_kernel<<<dim3(F_IN / 32, HDIM / 32), dim3(32, 8)>>>(W1, F_IN, HDIM);
    gemm_mma<128, false, 0><<<ggrid, 256>>>(x, N);
    gather_kernel<<<GB, 256>>>(b1, N, 0);

    // layer 2: g_H = relu(g_A) @ W2 ; g_A2 = gather(b2)
    wtrans_kernel<<<dim3(HDIM / 32, HDIM / 32), dim3(32, 8)>>>(W2, HDIM, HDIM);
    gemm_mma<256, true, 1><<<ggrid, 256>>>(nullptr, N);
    gather_kernel<<<GB, 256>>>(b2, N, 1);

    // classifier: out = relu(g_A2) @ Wc + bc (tf32 mma)
    wtrans_kernel<<<dim3(HDIM / 32, 1), dim3(32, 8)>>>(Wc, HDIM, 32);
    gemm_cls<<<RB, 256>>>(bc, out, N);

    (void)n_in; (void)out_size;
}